// round 2
// baseline (speedup 1.0000x reference)
#include <cuda_runtime.h>

// gltrivmlp: out[b,g,0:16]=con, out[...,16:32]=clip(con*s),
// out[...,32:48]=clip^2, out[...,48:64]=clip^3, s=rowsum(mat[b,g,:])/16.
// The 10-iteration reference loop is a 16-lane shift register reaching this
// fixed point after 3 iterations; initial val[16:64] is dead.
//
// R2: 4 rows/warp, grid=1024 blocks -> single resident wave (<=1184 blocks
// of capacity at ~7 blocks/SM), streaming loads (__ldcs), all shfl-reduces
// and stores deferred to one tail so the warp issues loads continuously.

#define GS    1024
#define PARAM 64
#define RPW   4      // rows per warp

__global__ __launch_bounds__(256)
void gltrivmlp_kernel(const float* __restrict__ mat,
                      const float* __restrict__ val,
                      float* __restrict__ out,
                      int rows)
{
    int warp = (int)((blockIdx.x * (unsigned)blockDim.x + threadIdx.x) >> 5);
    int lane = threadIdx.x & 31;
    int r0 = warp * RPW;
    if (r0 >= rows) return;

    // ---- phase 1: lane-partial sums for 4 rows, pure load+FADD stream
    float acc[RPW];
    #pragma unroll
    for (int r = 0; r < RPW; r++) {
        const float4* m = reinterpret_cast<const float4*>(mat + (size_t)(r0 + r) * GS);
        float4 v0 = __ldcs(&m[lane +   0]);
        float4 v1 = __ldcs(&m[lane +  32]);
        float4 v2 = __ldcs(&m[lane +  64]);
        float4 v3 = __ldcs(&m[lane +  96]);
        float4 v4 = __ldcs(&m[lane + 128]);
        float4 v5 = __ldcs(&m[lane + 160]);
        float4 v6 = __ldcs(&m[lane + 192]);
        float4 v7 = __ldcs(&m[lane + 224]);
        float a0 = ((v0.x + v0.y) + (v0.z + v0.w)) + ((v1.x + v1.y) + (v1.z + v1.w));
        float a1 = ((v2.x + v2.y) + (v2.z + v2.w)) + ((v3.x + v3.y) + (v3.z + v3.w));
        float a2 = ((v4.x + v4.y) + (v4.z + v4.w)) + ((v5.x + v5.y) + (v5.z + v5.w));
        float a3 = ((v6.x + v6.y) + (v6.z + v6.w)) + ((v7.x + v7.y) + (v7.z + v7.w));
        acc[r] = (a0 + a1) + (a2 + a3);
    }

    // ---- phase 2: warp reductions (deferred, amortized over 4 rows)
    #pragma unroll
    for (int r = 0; r < RPW; r++) {
        float s = acc[r];
        #pragma unroll
        for (int o = 16; o > 0; o >>= 1)
            s += __shfl_xor_sync(0xFFFFFFFFu, s, o);
        acc[r] = s * (1.0f / 16.0f);
    }

    // ---- phase 3: outputs. lane -> elements {2*lane, 2*lane+1}, same group g
    int e0 = lane << 1;
    int g  = e0 >> 4;          // number of clip applications: 0..3
    #pragma unroll
    for (int r = 0; r < RPW; r++) {
        const float* con = val + (size_t)(r0 + r) * PARAM;
        float x0 = __ldg(&con[e0 & 15]);
        float x1 = __ldg(&con[(e0 + 1) & 15]);
        float sc = acc[r];
        #pragma unroll
        for (int i = 0; i < 3; i++) {
            if (i < g) {
                x0 = fminf(fmaxf(x0 * sc, -1.0f), 1.0f);
                x1 = fminf(fmaxf(x1 * sc, -1.0f), 1.0f);
            }
        }
        float2* op = reinterpret_cast<float2*>(out + (size_t)(r0 + r) * PARAM);
        op[lane] = make_float2(x0, x1);
    }
}

extern "C" void kernel_launch(void* const* d_in, const int* in_sizes, int n_in,
                              void* d_out, int out_size)
{
    const float* mat = (const float*)d_in[0];   // (32,1024,1024) f32
    const float* val = (const float*)d_in[1];   // (32,1024,64)  f32
    float* out = (float*)d_out;                 // (32,1024,64)  f32

    int rows = in_sizes[0] / GS;                // 32768
    int warps = (rows + RPW - 1) / RPW;         // 8192
    int blocks = (warps + 7) / 8;               // 1024 blocks of 256 threads
    gltrivmlp_kernel<<<blocks, 256>>>(mat, val, out, rows);
}

// round 3
// speedup vs baseline: 1.0764x; 1.0764x over previous
#include <cuda_runtime.h>

// gltrivmlp: out[b,g,0:16]=con, out[...,16:32]=clip(con*s),
// out[...,32:48]=clip^2, out[...,48:64]=clip^3, s=rowsum(mat[b,g,:])/16.
// (10-iter reference loop is a 16-lane shift register; fixed point after 3
// iterations; initial val[16:64] is dead.)
//
// R3: persistent grid — exactly 148 SMs * 8 blocks = 1184 CTAs, all resident
// (__launch_bounds__(256,8) pins regs<=32). Each warp grid-strides 1 row at a
// time (R1's proven load structure), eliminating the 3 wave transitions that
// cost R1 ~4us while keeping fine-grained backfill against CTA spread.

#define GS    1024
#define PARAM 64
#define NSM   148
#define BLKS  (NSM * 8)

__global__ __launch_bounds__(256, 8)
void gltrivmlp_kernel(const float* __restrict__ mat,
                      const float* __restrict__ val,
                      float* __restrict__ out,
                      int rows)
{
    const int lane = threadIdx.x & 31;
    const int gw   = blockIdx.x * 8 + (threadIdx.x >> 5);   // global warp id
    const int totw = BLKS * 8;                               // 9472 warps

    // output mapping: lane -> elements {2*lane, 2*lane+1}; both in group g
    const int e0 = lane << 1;
    const int g  = e0 >> 4;          // clip applications: 0..3

    for (int row = gw; row < rows; row += totw) {
        const float4* m = reinterpret_cast<const float4*>(mat + (size_t)row * GS);

        float4 v0 = __ldcs(&m[lane +  0]);
        float4 v1 = __ldcs(&m[lane + 32]);
        float4 v2 = __ldcs(&m[lane + 64]);
        float4 v3 = __ldcs(&m[lane + 96]);
        float a0 = ((v0.x + v0.y) + (v0.z + v0.w)) + ((v1.x + v1.y) + (v1.z + v1.w));
        float a1 = ((v2.x + v2.y) + (v2.z + v2.w)) + ((v3.x + v3.y) + (v3.z + v3.w));
        float4 v4 = __ldcs(&m[lane + 128]);
        float4 v5 = __ldcs(&m[lane + 160]);
        float4 v6 = __ldcs(&m[lane + 192]);
        float4 v7 = __ldcs(&m[lane + 224]);
        float a2 = ((v4.x + v4.y) + (v4.z + v4.w)) + ((v5.x + v5.y) + (v5.z + v5.w));
        float a3 = ((v6.x + v6.y) + (v6.z + v6.w)) + ((v7.x + v7.y) + (v7.z + v7.w));

        float s = (a0 + a1) + (a2 + a3);
        #pragma unroll
        for (int o = 16; o > 0; o >>= 1)
            s += __shfl_xor_sync(0xFFFFFFFFu, s, o);
        const float scale = s * (1.0f / 16.0f);

        const float* con = val + (size_t)row * PARAM;
        float x0 = __ldg(&con[e0 & 15]);
        float x1 = __ldg(&con[(e0 + 1) & 15]);
        #pragma unroll
        for (int i = 0; i < 3; i++) {
            if (i < g) {
                x0 = fminf(fmaxf(x0 * scale, -1.0f), 1.0f);
                x1 = fminf(fmaxf(x1 * scale, -1.0f), 1.0f);
            }
        }
        float2* op = reinterpret_cast<float2*>(out + (size_t)row * PARAM);
        op[lane] = make_float2(x0, x1);
    }
}

extern "C" void kernel_launch(void* const* d_in, const int* in_sizes, int n_in,
                              void* d_out, int out_size)
{
    const float* mat = (const float*)d_in[0];   // (32,1024,1024) f32
    const float* val = (const float*)d_in[1];   // (32,1024,64)  f32
    float* out = (float*)d_out;                 // (32,1024,64)  f32

    int rows = in_sizes[0] / GS;                // 32768
    gltrivmlp_kernel<<<BLKS, 256>>>(mat, val, out, rows);
}